// round 1
// baseline (speedup 1.0000x reference)
#include <cuda_runtime.h>

#define NI    9
#define NM3   165     // # monomials of degree 3 (i<=j<=l)
#define NM2   45      // # monomials of degree 2 (i<=j)
#define ST3   32      // padded deg-3 column stride (23 or 30 -> 32)
#define ST2   4       // padded deg-2 column stride (3 or 4 -> 4)
#define CDIM  256
#define EDIM  10

// Symmetrized, padded U tables. pass 0 = scalar channel, pass 1..3 = vector a=0..2.
__device__ __align__(16) float g_T3[4][NM3 * ST3];  // 84.5 KB
__device__ __align__(16) float g_T2[4][NM2 * ST2];  // 2.9 KB

__device__ __forceinline__ void decode3(int m, int& i, int& j, int& l) {
    int cnt = 0;
    for (int a = 0; a < NI; a++)
        for (int b = a; b < NI; b++)
            for (int c = b; c < NI; c++) {
                if (cnt == m) { i = a; j = b; l = c; return; }
                cnt++;
            }
    i = j = l = 0;
}

__device__ __forceinline__ void decode2(int m, int& i, int& j) {
    int cnt = 0;
    for (int a = 0; a < NI; a++)
        for (int b = a; b < NI; b++) {
            if (cnt == m) { i = a; j = b; return; }
            cnt++;
        }
    i = j = 0;
}

// Build symmetrized tables: T3[m][k] = sum over distinct permutations p of the
// sorted triple m of U3[p1,p2,p3,k]; likewise T2 for pairs. Padding cols = 0.
__global__ void precompute_kernel(const float* __restrict__ U2s,
                                  const float* __restrict__ U3s,
                                  const float* __restrict__ U2v,
                                  const float* __restrict__ U3v) {
    int t = blockIdx.x * blockDim.x + threadIdx.x;
    const int N3 = 4 * NM3 * ST3;  // 21120
    const int N2 = 4 * NM2 * ST2;  // 720
    if (t < N3) {
        int pass = t / (NM3 * ST3);
        int r = t % (NM3 * ST3);
        int m = r / ST3, k = r % ST3;
        int K = (pass == 0) ? 23 : 30;
        float val = 0.f;
        if (k < K) {
            int i, j, l;
            decode3(m, i, j, l);
            int pi[6] = { i, i, j, j, l, l };
            int pj[6] = { j, l, i, l, i, j };
            int pl[6] = { l, j, l, i, j, i };
            const float* base = (pass == 0) ? U3s : (U3v + (pass - 1) * (NI * NI * NI * 30));
            int codes[6];
            for (int p = 0; p < 6; p++) {
                int code = (pi[p] * NI + pj[p]) * NI + pl[p];
                bool dup = false;
                for (int q = 0; q < p; q++)
                    if (codes[q] == code) dup = true;
                codes[p] = code;
                if (!dup) val += base[code * K + k];
            }
        }
        g_T3[pass][m * ST3 + k] = val;
    } else if (t < N3 + N2) {
        int u = t - N3;
        int pass = u / (NM2 * ST2);
        int r = u % (NM2 * ST2);
        int m = r / ST2, k = r % ST2;
        int K = (pass == 0) ? 3 : 4;
        float val = 0.f;
        if (k < K) {
            int i, j;
            decode2(m, i, j);
            const float* base = (pass == 0) ? U2s : (U2v + (pass - 1) * (NI * NI * 4));
            val = base[(i * NI + j) * K + k];
            if (i != j) val += base[(j * NI + i) * K + k];
        }
        g_T2[pass][m * ST2 + k] = val;
    }
}

// Per-pass epilogue: res = sum_k wy3[k]*acc[k] + sum_k wy2[k]*a2[k] + wy1*<U1,x>
// wy computed inline from W (L2-resident, coalesced in c) and y (shared).
template <int K3, int K2>
__device__ __forceinline__ float epilogue(const float* __restrict__ acc,
                                          const float* __restrict__ a2,
                                          const float* __restrict__ W3,
                                          const float* __restrict__ W2,
                                          const float* __restrict__ W1,
                                          const float* __restrict__ U1,
                                          const float* __restrict__ sy,
                                          const float* __restrict__ sxr, int c) {
    float res = 0.f;
#pragma unroll
    for (int k = 0; k < K3; k++) {
        float w = 0.f;
#pragma unroll
        for (int e = 0; e < EDIM; e++) w = fmaf(W3[(e * K3 + k) * CDIM + c], sy[e], w);
        res = fmaf(w, acc[k], res);
    }
#pragma unroll
    for (int k = 0; k < K2; k++) {
        float w = 0.f;
#pragma unroll
        for (int e = 0; e < EDIM; e++) w = fmaf(W2[(e * K2 + k) * CDIM + c], sy[e], w);
        res = fmaf(w, a2[k], res);
    }
    float d1 = 0.f;
#pragma unroll
    for (int i = 0; i < NI; i++) d1 = fmaf(U1[i], sxr[i], d1);
    float w1 = 0.f;
#pragma unroll
    for (int e = 0; e < EDIM; e++) w1 = fmaf(W1[e * CDIM + c], sy[e], w1);
    return fmaf(w1, d1, res);
}

__global__ void __launch_bounds__(CDIM)
sc_main_kernel(const float* __restrict__ x, const float* __restrict__ y,
               const float* __restrict__ U1s, const float* __restrict__ U1v,
               const float* __restrict__ W1s, const float* __restrict__ W2s,
               const float* __restrict__ W3s, const float* __restrict__ W1v,
               const float* __restrict__ W2v, const float* __restrict__ W3v,
               float* __restrict__ out) {
    __shared__ __align__(16) float sT3[NM3 * ST3];   // 21.1 KB staged per pass
    __shared__ __align__(16) float sT2[NM2 * ST2];
    __shared__ float sx[CDIM * NI];                  // 9.2 KB, x rows for this b
    __shared__ float sy[EDIM];

    const int b = blockIdx.x;
    const int c = threadIdx.x;

    for (int t = c; t < CDIM * NI; t += CDIM) sx[t] = x[b * (CDIM * NI) + t];
    if (c < EDIM) sy[c] = y[b * EDIM + c];

    const float* sxr = &sx[c * NI];  // stride-9 rows: (9c+i) mod 32 is conflict-free

    for (int pass = 0; pass < 4; pass++) {
        __syncthreads();  // protect previous-pass table reads; also covers sx/sy init
        {
            const float4* src3 = (const float4*)&g_T3[pass][0];
            float4* dst3 = (float4*)sT3;
            for (int t = c; t < NM3 * ST3 / 4; t += CDIM) dst3[t] = src3[t];
            const float4* src2 = (const float4*)&g_T2[pass][0];
            float4* dst2 = (float4*)sT2;
            for (int t = c; t < NM2 * ST2 / 4; t += CDIM) dst2[t] = src2[t];
        }
        __syncthreads();

        float acc[ST3];
#pragma unroll
        for (int q = 0; q < ST3; q++) acc[q] = 0.f;
        float a2[4] = { 0.f, 0.f, 0.f, 0.f };

        const float4* row = (const float4*)sT3;    // broadcast reads (same addr per warp)
        const float4* row2 = (const float4*)sT2;

        for (int i = 0; i < NI; i++) {
            float xi = sxr[i];
            for (int j = i; j < NI; j++) {
                float xij = xi * sxr[j];
                float4 u2 = *row2++;
                a2[0] = fmaf(u2.x, xij, a2[0]);
                a2[1] = fmaf(u2.y, xij, a2[1]);
                a2[2] = fmaf(u2.z, xij, a2[2]);
                a2[3] = fmaf(u2.w, xij, a2[3]);
                for (int l = j; l < NI; l++) {
                    float mono = xij * sxr[l];
#pragma unroll
                    for (int q = 0; q < 8; q++) {
                        float4 u = row[q];
                        acc[4 * q + 0] = fmaf(u.x, mono, acc[4 * q + 0]);
                        acc[4 * q + 1] = fmaf(u.y, mono, acc[4 * q + 1]);
                        acc[4 * q + 2] = fmaf(u.z, mono, acc[4 * q + 2]);
                        acc[4 * q + 3] = fmaf(u.w, mono, acc[4 * q + 3]);
                    }
                    row += 8;
                }
            }
        }

        if (pass == 0) {
            float res = epilogue<23, 3>(acc, a2, W3s, W2s, W1s, U1s, sy, sxr, c);
            out[b * 1024 + c] = res;
        } else {
            int a = pass - 1;
            float res = epilogue<30, 4>(acc, a2, W3v, W2v, W1v, U1v + a * NI, sy, sxr, c);
            out[b * 1024 + 256 + c * 3 + a] = res;
        }
    }
}

extern "C" void kernel_launch(void* const* d_in, const int* in_sizes, int n_in,
                              void* d_out, int out_size) {
    const float* x   = (const float*)d_in[0];
    const float* y   = (const float*)d_in[1];
    const float* U1s = (const float*)d_in[2];
    const float* U2s = (const float*)d_in[3];
    const float* U3s = (const float*)d_in[4];
    const float* U1v = (const float*)d_in[5];
    const float* U2v = (const float*)d_in[6];
    const float* U3v = (const float*)d_in[7];
    const float* W1s = (const float*)d_in[8];
    const float* W2s = (const float*)d_in[9];
    const float* W3s = (const float*)d_in[10];
    const float* W1v = (const float*)d_in[11];
    const float* W2v = (const float*)d_in[12];
    const float* W3v = (const float*)d_in[13];
    float* out = (float*)d_out;

    const int B = in_sizes[0] / (CDIM * NI);  // 2048

    const int total = 4 * NM3 * ST3 + 4 * NM2 * ST2;
    precompute_kernel<<<(total + 255) / 256, 256>>>(U2s, U3s, U2v, U3v);
    sc_main_kernel<<<B, CDIM>>>(x, y, U1s, U1v, W1s, W2s, W3s, W1v, W2v, W3v, out);
}

// round 2
// speedup vs baseline: 1.5339x; 1.5339x over previous
#include <cuda_runtime.h>

#define NI    9
#define NM3   165     // # monomials of degree 3 (i<=j<=l)
#define NM2   45      // # monomials of degree 2 (i<=j)
#define ST3   32      // padded deg-3 column stride (23 or 30 -> 32)
#define CDIM  256
#define EDIM  10
#define NB    2       // batches per CTA

typedef unsigned long long ull;

// Symmetrized, padded U tables. pass 0 = scalar channel, pass 1..3 = vector a=0..2.
__device__ __align__(16) float g_T3[4][NM3 * ST3];
__device__ __align__(16) float g_T2[4][NM2 * 4];

__device__ __forceinline__ void decode3(int m, int& i, int& j, int& l) {
    int cnt = 0;
    for (int a = 0; a < NI; a++)
        for (int b = a; b < NI; b++)
            for (int c = b; c < NI; c++) {
                if (cnt == m) { i = a; j = b; l = c; return; }
                cnt++;
            }
    i = j = l = 0;
}

__device__ __forceinline__ void decode2(int m, int& i, int& j) {
    int cnt = 0;
    for (int a = 0; a < NI; a++)
        for (int b = a; b < NI; b++) {
            if (cnt == m) { i = a; j = b; return; }
            cnt++;
        }
    i = j = 0;
}

__global__ void precompute_kernel(const float* __restrict__ U2s,
                                  const float* __restrict__ U3s,
                                  const float* __restrict__ U2v,
                                  const float* __restrict__ U3v) {
    int t = blockIdx.x * blockDim.x + threadIdx.x;
    const int N3 = 4 * NM3 * ST3;
    const int N2 = 4 * NM2 * 4;
    if (t < N3) {
        int pass = t / (NM3 * ST3);
        int r = t % (NM3 * ST3);
        int m = r / ST3, k = r % ST3;
        int K = (pass == 0) ? 23 : 30;
        float val = 0.f;
        if (k < K) {
            int i, j, l;
            decode3(m, i, j, l);
            int pi[6] = { i, i, j, j, l, l };
            int pj[6] = { j, l, i, l, i, j };
            int pl[6] = { l, j, l, i, j, i };
            const float* base = (pass == 0) ? U3s : (U3v + (pass - 1) * (NI * NI * NI * 30));
            int codes[6];
            for (int p = 0; p < 6; p++) {
                int code = (pi[p] * NI + pj[p]) * NI + pl[p];
                bool dup = false;
                for (int q = 0; q < p; q++)
                    if (codes[q] == code) dup = true;
                codes[p] = code;
                if (!dup) val += base[code * K + k];
            }
        }
        g_T3[pass][m * ST3 + k] = val;
    } else if (t < N3 + N2) {
        int u = t - N3;
        int pass = u / (NM2 * 4);
        int r = u % (NM2 * 4);
        int m = r / 4, k = r % 4;
        int K = (pass == 0) ? 3 : 4;
        float val = 0.f;
        if (k < K) {
            int i, j;
            decode2(m, i, j);
            const float* base = (pass == 0) ? U2s : (U2v + (pass - 1) * (NI * NI * 4));
            val = base[(i * NI + j) * K + k];
            if (i != j) val += base[(j * NI + i) * K + k];
        }
        g_T2[pass][m * 4 + k] = val;
    }
}

// ---- packed f32x2 helpers ----
__device__ __forceinline__ ull pack2(float x) {
    ull r; asm("mov.b64 %0, {%1, %1};" : "=l"(r) : "f"(x)); return r;
}
__device__ __forceinline__ void fma2(ull& d, ull a, ull b) {
    asm("fma.rn.f32x2 %0, %1, %2, %0;" : "+l"(d) : "l"(a), "l"(b));
}
__device__ __forceinline__ void unpack2(ull v, float& lo, float& hi) {
    asm("mov.b64 {%0, %1}, %2;" : "=f"(lo), "=f"(hi) : "l"(v));
}

// Monomial sweep for one pass, two batches. NQ = # ulonglong2 (4-col groups) per row.
template <int NQ>
__device__ __forceinline__ void sweep(const float* __restrict__ sT3,
                                      const float* __restrict__ sT2,
                                      const float* __restrict__ sxr0,
                                      const float* __restrict__ sxr1,
                                      ull* __restrict__ acc0, ull* __restrict__ acc1,
                                      ull* __restrict__ a20, ull* __restrict__ a21) {
    const ulonglong2* row  = (const ulonglong2*)sT3;
    const ulonglong2* row2 = (const ulonglong2*)sT2;
    for (int i = 0; i < NI; i++) {
        float xi0 = sxr0[i], xi1 = sxr1[i];
        for (int j = i; j < NI; j++) {
            float xij0 = xi0 * sxr0[j], xij1 = xi1 * sxr1[j];
            ulonglong2 u2 = *row2++;
            ull p0 = pack2(xij0), p1 = pack2(xij1);
            fma2(a20[0], u2.x, p0); fma2(a20[1], u2.y, p0);
            fma2(a21[0], u2.x, p1); fma2(a21[1], u2.y, p1);
            for (int l = j; l < NI; l++) {
                ull m0 = pack2(xij0 * sxr0[l]);
                ull m1 = pack2(xij1 * sxr1[l]);
#pragma unroll
                for (int q = 0; q < NQ; q++) {
                    ulonglong2 t = row[q];
                    fma2(acc0[2 * q],     t.x, m0);
                    fma2(acc0[2 * q + 1], t.y, m0);
                    fma2(acc1[2 * q],     t.x, m1);
                    fma2(acc1[2 * q + 1], t.y, m1);
                }
                row += ST3 / 4;  // 8 ulonglong2 per row (stride fixed at 32 cols)
            }
        }
    }
}

// Full pass: sweep + epilogue for two batches. Returns res0, res1.
template <int NQ, int K3, int K2>
__device__ __forceinline__ void do_pass(const float* __restrict__ sT3,
                                        const float* __restrict__ sT2,
                                        const float* __restrict__ sxr0,
                                        const float* __restrict__ sxr1,
                                        const float* __restrict__ sy0,
                                        const float* __restrict__ sy1,
                                        const float* __restrict__ W3,
                                        const float* __restrict__ W2,
                                        const float* __restrict__ W1,
                                        const float* __restrict__ U1,
                                        int c, float& res0, float& res1) {
    ull acc0[2 * NQ], acc1[2 * NQ], a20[2], a21[2];
#pragma unroll
    for (int q = 0; q < 2 * NQ; q++) { acc0[q] = 0ull; acc1[q] = 0ull; }
    a20[0] = a20[1] = a21[0] = a21[1] = 0ull;

    sweep<NQ>(sT3, sT2, sxr0, sxr1, acc0, acc1, a20, a21);

    float af0[4 * NQ], af1[4 * NQ], a2f0[4], a2f1[4];
#pragma unroll
    for (int q = 0; q < 2 * NQ; q++) {
        unpack2(acc0[q], af0[2 * q], af0[2 * q + 1]);
        unpack2(acc1[q], af1[2 * q], af1[2 * q + 1]);
    }
    unpack2(a20[0], a2f0[0], a2f0[1]); unpack2(a20[1], a2f0[2], a2f0[3]);
    unpack2(a21[0], a2f1[0], a2f1[1]); unpack2(a21[1], a2f1[2], a2f1[3]);

    float r0 = 0.f, r1 = 0.f;
#pragma unroll
    for (int k = 0; k < K3; k++) {
        float w0 = 0.f, w1 = 0.f;
#pragma unroll
        for (int e = 0; e < EDIM; e++) {
            float wv = W3[(e * K3 + k) * CDIM + c];   // reused for both batches
            w0 = fmaf(wv, sy0[e], w0);
            w1 = fmaf(wv, sy1[e], w1);
        }
        r0 = fmaf(w0, af0[k], r0);
        r1 = fmaf(w1, af1[k], r1);
    }
#pragma unroll
    for (int k = 0; k < K2; k++) {
        float w0 = 0.f, w1 = 0.f;
#pragma unroll
        for (int e = 0; e < EDIM; e++) {
            float wv = W2[(e * K2 + k) * CDIM + c];
            w0 = fmaf(wv, sy0[e], w0);
            w1 = fmaf(wv, sy1[e], w1);
        }
        r0 = fmaf(w0, a2f0[k], r0);
        r1 = fmaf(w1, a2f1[k], r1);
    }
    float d10 = 0.f, d11 = 0.f;
#pragma unroll
    for (int i = 0; i < NI; i++) {
        d10 = fmaf(U1[i], sxr0[i], d10);
        d11 = fmaf(U1[i], sxr1[i], d11);
    }
    float w10 = 0.f, w11 = 0.f;
#pragma unroll
    for (int e = 0; e < EDIM; e++) {
        float wv = W1[e * CDIM + c];
        w10 = fmaf(wv, sy0[e], w10);
        w11 = fmaf(wv, sy1[e], w11);
    }
    res0 = fmaf(w10, d10, r0);
    res1 = fmaf(w11, d11, r1);
}

__global__ void __launch_bounds__(CDIM, 2)
sc_main_kernel(const float* __restrict__ x, const float* __restrict__ y,
               const float* __restrict__ U1s, const float* __restrict__ U1v,
               const float* __restrict__ W1s, const float* __restrict__ W2s,
               const float* __restrict__ W3s, const float* __restrict__ W1v,
               const float* __restrict__ W2v, const float* __restrict__ W3v,
               float* __restrict__ out) {
    __shared__ __align__(16) float sT3[NM3 * ST3];   // 21.1 KB
    __shared__ __align__(16) float sT2[NM2 * 4];
    __shared__ __align__(16) float sx[NB][CDIM * NI];  // 18.4 KB
    __shared__ float sy[NB][16];

    const int b0 = blockIdx.x * NB;
    const int c = threadIdx.x;

    {
        const float4* src = (const float4*)(x + (size_t)b0 * (CDIM * NI));
        float4* dst = (float4*)&sx[0][0];
        for (int t = c; t < NB * CDIM * NI / 4; t += CDIM) dst[t] = src[t];
        if (c < NB * EDIM) sy[c / EDIM][c % EDIM] = y[b0 * EDIM + c];
    }

    const float* sxr0 = &sx[0][c * NI];   // stride-9 rows: conflict-free mod 32
    const float* sxr1 = &sx[1][c * NI];
    const float* sy0 = &sy[0][0];
    const float* sy1 = &sy[1][0];

    for (int pass = 0; pass < 4; pass++) {
        __syncthreads();  // protects previous-pass table reads (and initial staging)
        {
            const float4* s3 = (const float4*)g_T3[pass];
            float4* d3 = (float4*)sT3;
            for (int t = c; t < NM3 * ST3 / 4; t += CDIM) d3[t] = s3[t];
            if (c < NM2) ((float4*)sT2)[c] = ((const float4*)g_T2[pass])[c];
        }
        __syncthreads();

        if (pass == 0) {
            float res0, res1;
            do_pass<6, 23, 3>(sT3, sT2, sxr0, sxr1, sy0, sy1,
                              W3s, W2s, W1s, U1s, c, res0, res1);
            out[(size_t)b0 * 1024 + c] = res0;
            out[(size_t)(b0 + 1) * 1024 + c] = res1;
        } else {
            int a = pass - 1;
            float res0, res1;
            do_pass<8, 30, 4>(sT3, sT2, sxr0, sxr1, sy0, sy1,
                              W3v, W2v, W1v, U1v + a * NI, c, res0, res1);
            out[(size_t)b0 * 1024 + 256 + c * 3 + a] = res0;
            out[(size_t)(b0 + 1) * 1024 + 256 + c * 3 + a] = res1;
        }
    }
}

extern "C" void kernel_launch(void* const* d_in, const int* in_sizes, int n_in,
                              void* d_out, int out_size) {
    const float* x   = (const float*)d_in[0];
    const float* y   = (const float*)d_in[1];
    const float* U1s = (const float*)d_in[2];
    const float* U2s = (const float*)d_in[3];
    const float* U3s = (const float*)d_in[4];
    const float* U1v = (const float*)d_in[5];
    const float* U2v = (const float*)d_in[6];
    const float* U3v = (const float*)d_in[7];
    const float* W1s = (const float*)d_in[8];
    const float* W2s = (const float*)d_in[9];
    const float* W3s = (const float*)d_in[10];
    const float* W1v = (const float*)d_in[11];
    const float* W2v = (const float*)d_in[12];
    const float* W3v = (const float*)d_in[13];
    float* out = (float*)d_out;

    const int B = in_sizes[0] / (CDIM * NI);  // 2048

    const int total = 4 * NM3 * ST3 + 4 * NM2 * 4;
    precompute_kernel<<<(total + 255) / 256, 256>>>(U2s, U3s, U2v, U3v);
    sc_main_kernel<<<B / NB, CDIM>>>(x, y, U1s, U1v, W1s, W2s, W3s, W1v, W2v, W3v, out);
}

// round 3
// speedup vs baseline: 1.5343x; 1.0003x over previous
#include <cuda_runtime.h>

#define NI    9
#define NM3   165     // # monomials of degree 3 (i<=j<=l)
#define NM2   45      // # monomials of degree 2 (i<=j)
#define ST3   32      // padded deg-3 column stride (23 or 30 -> 32)
#define CDIM  256
#define EDIM  10
#define NB    2       // batches per CTA

typedef unsigned long long ull;

// Symmetrized, padded U tables. pass 0 = scalar channel, pass 1..3 = vector a=0..2.
__device__ __align__(16) float g_T3[4][NM3 * ST3];
__device__ __align__(16) float g_T2[4][NM2 * 4];

__device__ __forceinline__ void decode3(int m, int& i, int& j, int& l) {
    int cnt = 0;
    for (int a = 0; a < NI; a++)
        for (int b = a; b < NI; b++)
            for (int c = b; c < NI; c++) {
                if (cnt == m) { i = a; j = b; l = c; return; }
                cnt++;
            }
    i = j = l = 0;
}

__device__ __forceinline__ void decode2(int m, int& i, int& j) {
    int cnt = 0;
    for (int a = 0; a < NI; a++)
        for (int b = a; b < NI; b++) {
            if (cnt == m) { i = a; j = b; return; }
            cnt++;
        }
    i = j = 0;
}

__global__ void precompute_kernel(const float* __restrict__ U2s,
                                  const float* __restrict__ U3s,
                                  const float* __restrict__ U2v,
                                  const float* __restrict__ U3v) {
    int t = blockIdx.x * blockDim.x + threadIdx.x;
    const int N3 = 4 * NM3 * ST3;
    const int N2 = 4 * NM2 * 4;
    if (t < N3) {
        int pass = t / (NM3 * ST3);
        int r = t % (NM3 * ST3);
        int m = r / ST3, k = r % ST3;
        int K = (pass == 0) ? 23 : 30;
        float val = 0.f;
        if (k < K) {
            int i, j, l;
            decode3(m, i, j, l);
            int pi[6] = { i, i, j, j, l, l };
            int pj[6] = { j, l, i, l, i, j };
            int pl[6] = { l, j, l, i, j, i };
            const float* base = (pass == 0) ? U3s : (U3v + (pass - 1) * (NI * NI * NI * 30));
            int codes[6];
            for (int p = 0; p < 6; p++) {
                int code = (pi[p] * NI + pj[p]) * NI + pl[p];
                bool dup = false;
                for (int q = 0; q < p; q++)
                    if (codes[q] == code) dup = true;
                codes[p] = code;
                if (!dup) val += base[code * K + k];
            }
        }
        g_T3[pass][m * ST3 + k] = val;
    } else if (t < N3 + N2) {
        int u = t - N3;
        int pass = u / (NM2 * 4);
        int r = u % (NM2 * 4);
        int m = r / 4, k = r % 4;
        int K = (pass == 0) ? 3 : 4;
        float val = 0.f;
        if (k < K) {
            int i, j;
            decode2(m, i, j);
            const float* base = (pass == 0) ? U2s : (U2v + (pass - 1) * (NI * NI * 4));
            val = base[(i * NI + j) * K + k];
            if (i != j) val += base[(j * NI + i) * K + k];
        }
        g_T2[pass][m * 4 + k] = val;
    }
}

// ---- packed f32x2 helpers ----
__device__ __forceinline__ ull pack2(float x) {
    ull r; asm("mov.b64 %0, {%1, %1};" : "=l"(r) : "f"(x)); return r;
}
__device__ __forceinline__ void fma2(ull& d, ull a, ull b) {
    asm("fma.rn.f32x2 %0, %1, %2, %0;" : "+l"(d) : "l"(a), "l"(b));
}
__device__ __forceinline__ void unpack2(ull v, float& lo, float& hi) {
    asm("mov.b64 {%0, %1}, %2;" : "=f"(lo), "=f"(hi) : "l"(v));
}

// Monomial sweep for one pass, two batches. NQ = # ulonglong2 (4-col groups) per row.
template <int NQ>
__device__ __forceinline__ void sweep(const float* __restrict__ sT3,
                                      const float* __restrict__ sT2,
                                      const float* __restrict__ sxr0,
                                      const float* __restrict__ sxr1,
                                      ull* __restrict__ acc0, ull* __restrict__ acc1,
                                      ull* __restrict__ a20, ull* __restrict__ a21) {
    const ulonglong2* row  = (const ulonglong2*)sT3;
    const ulonglong2* row2 = (const ulonglong2*)sT2;
    for (int i = 0; i < NI; i++) {
        float xi0 = sxr0[i], xi1 = sxr1[i];
        for (int j = i; j < NI; j++) {
            float xij0 = xi0 * sxr0[j], xij1 = xi1 * sxr1[j];
            ulonglong2 u2 = *row2++;
            ull p0 = pack2(xij0), p1 = pack2(xij1);
            fma2(a20[0], u2.x, p0); fma2(a20[1], u2.y, p0);
            fma2(a21[0], u2.x, p1); fma2(a21[1], u2.y, p1);
            for (int l = j; l < NI; l++) {
                ull m0 = pack2(xij0 * sxr0[l]);
                ull m1 = pack2(xij1 * sxr1[l]);
#pragma unroll
                for (int q = 0; q < NQ; q++) {
                    ulonglong2 t = row[q];
                    fma2(acc0[2 * q],     t.x, m0);
                    fma2(acc0[2 * q + 1], t.y, m0);
                    fma2(acc1[2 * q],     t.x, m1);
                    fma2(acc1[2 * q + 1], t.y, m1);
                }
                row += ST3 / 4;  // 8 ulonglong2 per row (stride fixed at 32 cols)
            }
        }
    }
}

// Full pass: sweep + epilogue for two batches. Returns res0, res1.
template <int NQ, int K3, int K2>
__device__ __forceinline__ void do_pass(const float* __restrict__ sT3,
                                        const float* __restrict__ sT2,
                                        const float* __restrict__ sxr0,
                                        const float* __restrict__ sxr1,
                                        const float* __restrict__ sy0,
                                        const float* __restrict__ sy1,
                                        const float* __restrict__ W3,
                                        const float* __restrict__ W2,
                                        const float* __restrict__ W1,
                                        const float* __restrict__ U1,
                                        int c, float& res0, float& res1) {
    ull acc0[2 * NQ], acc1[2 * NQ], a20[2], a21[2];
#pragma unroll
    for (int q = 0; q < 2 * NQ; q++) { acc0[q] = 0ull; acc1[q] = 0ull; }
    a20[0] = a20[1] = a21[0] = a21[1] = 0ull;

    sweep<NQ>(sT3, sT2, sxr0, sxr1, acc0, acc1, a20, a21);

    float af0[4 * NQ], af1[4 * NQ], a2f0[4], a2f1[4];
#pragma unroll
    for (int q = 0; q < 2 * NQ; q++) {
        unpack2(acc0[q], af0[2 * q], af0[2 * q + 1]);
        unpack2(acc1[q], af1[2 * q], af1[2 * q + 1]);
    }
    unpack2(a20[0], a2f0[0], a2f0[1]); unpack2(a20[1], a2f0[2], a2f0[3]);
    unpack2(a21[0], a2f1[0], a2f1[1]); unpack2(a21[1], a2f1[2], a2f1[3]);

    float r0 = 0.f, r1 = 0.f;
#pragma unroll
    for (int k = 0; k < K3; k++) {
        float w0 = 0.f, w1 = 0.f;
#pragma unroll
        for (int e = 0; e < EDIM; e++) {
            float wv = W3[(e * K3 + k) * CDIM + c];   // reused for both batches
            w0 = fmaf(wv, sy0[e], w0);
            w1 = fmaf(wv, sy1[e], w1);
        }
        r0 = fmaf(w0, af0[k], r0);
        r1 = fmaf(w1, af1[k], r1);
    }
#pragma unroll
    for (int k = 0; k < K2; k++) {
        float w0 = 0.f, w1 = 0.f;
#pragma unroll
        for (int e = 0; e < EDIM; e++) {
            float wv = W2[(e * K2 + k) * CDIM + c];
            w0 = fmaf(wv, sy0[e], w0);
            w1 = fmaf(wv, sy1[e], w1);
        }
        r0 = fmaf(w0, a2f0[k], r0);
        r1 = fmaf(w1, a2f1[k], r1);
    }
    float d10 = 0.f, d11 = 0.f;
#pragma unroll
    for (int i = 0; i < NI; i++) {
        d10 = fmaf(U1[i], sxr0[i], d10);
        d11 = fmaf(U1[i], sxr1[i], d11);
    }
    float w10 = 0.f, w11 = 0.f;
#pragma unroll
    for (int e = 0; e < EDIM; e++) {
        float wv = W1[e * CDIM + c];
        w10 = fmaf(wv, sy0[e], w10);
        w11 = fmaf(wv, sy1[e], w11);
    }
    res0 = fmaf(w10, d10, r0);
    res1 = fmaf(w11, d11, r1);
}

__global__ void __launch_bounds__(CDIM, 2)
sc_main_kernel(const float* __restrict__ x, const float* __restrict__ y,
               const float* __restrict__ U1s, const float* __restrict__ U1v,
               const float* __restrict__ W1s, const float* __restrict__ W2s,
               const float* __restrict__ W3s, const float* __restrict__ W1v,
               const float* __restrict__ W2v, const float* __restrict__ W3v,
               float* __restrict__ out) {
    __shared__ __align__(16) float sT3[NM3 * ST3];   // 21.1 KB
    __shared__ __align__(16) float sT2[NM2 * 4];
    __shared__ __align__(16) float sx[NB][CDIM * NI];  // 18.4 KB
    __shared__ float sy[NB][16];

    const int b0 = blockIdx.x * NB;
    const int c = threadIdx.x;

    {
        const float4* src = (const float4*)(x + (size_t)b0 * (CDIM * NI));
        float4* dst = (float4*)&sx[0][0];
        for (int t = c; t < NB * CDIM * NI / 4; t += CDIM) dst[t] = src[t];
        if (c < NB * EDIM) sy[c / EDIM][c % EDIM] = y[b0 * EDIM + c];
    }

    const float* sxr0 = &sx[0][c * NI];   // stride-9 rows: conflict-free mod 32
    const float* sxr1 = &sx[1][c * NI];
    const float* sy0 = &sy[0][0];
    const float* sy1 = &sy[1][0];

    for (int pass = 0; pass < 4; pass++) {
        __syncthreads();  // protects previous-pass table reads (and initial staging)
        {
            const float4* s3 = (const float4*)g_T3[pass];
            float4* d3 = (float4*)sT3;
            for (int t = c; t < NM3 * ST3 / 4; t += CDIM) d3[t] = s3[t];
            if (c < NM2) ((float4*)sT2)[c] = ((const float4*)g_T2[pass])[c];
        }
        __syncthreads();

        if (pass == 0) {
            float res0, res1;
            do_pass<6, 23, 3>(sT3, sT2, sxr0, sxr1, sy0, sy1,
                              W3s, W2s, W1s, U1s, c, res0, res1);
            out[(size_t)b0 * 1024 + c] = res0;
            out[(size_t)(b0 + 1) * 1024 + c] = res1;
        } else {
            int a = pass - 1;
            float res0, res1;
            do_pass<8, 30, 4>(sT3, sT2, sxr0, sxr1, sy0, sy1,
                              W3v, W2v, W1v, U1v + a * NI, c, res0, res1);
            out[(size_t)b0 * 1024 + 256 + c * 3 + a] = res0;
            out[(size_t)(b0 + 1) * 1024 + 256 + c * 3 + a] = res1;
        }
    }
}

extern "C" void kernel_launch(void* const* d_in, const int* in_sizes, int n_in,
                              void* d_out, int out_size) {
    const float* x   = (const float*)d_in[0];
    const float* y   = (const float*)d_in[1];
    const float* U1s = (const float*)d_in[2];
    const float* U2s = (const float*)d_in[3];
    const float* U3s = (const float*)d_in[4];
    const float* U1v = (const float*)d_in[5];
    const float* U2v = (const float*)d_in[6];
    const float* U3v = (const float*)d_in[7];
    const float* W1s = (const float*)d_in[8];
    const float* W2s = (const float*)d_in[9];
    const float* W3s = (const float*)d_in[10];
    const float* W1v = (const float*)d_in[11];
    const float* W2v = (const float*)d_in[12];
    const float* W3v = (const float*)d_in[13];
    float* out = (float*)d_out;

    const int B = in_sizes[0] / (CDIM * NI);  // 2048

    const int total = 4 * NM3 * ST3 + 4 * NM2 * 4;
    precompute_kernel<<<(total + 255) / 256, 256>>>(U2s, U3s, U2v, U3v);
    sc_main_kernel<<<B / NB, CDIM>>>(x, y, U1s, U1v, W1s, W2s, W3s, W1v, W2v, W3v, out);
}